// round 1
// baseline (speedup 1.0000x reference)
#include <cuda_runtime.h>

// FFTConv1d: y[b,o,t] = sum_{i,k} W[o,i,k] * x[b,i,t+63-k]  (zero-padded x)
// B=8, CIN=COUT=64, T=16384, K=127, crop start = 63 ('same', centered)

#define B_      8
#define CIN     64
#define COUT    64
#define T_      16384
#define KW      127
#define PAD     63
#define TT      128        // t-tile per block
#define RR      16         // outputs per thread
#define NGROUP  (TT / RR)  // 8 t-groups
#define NTHREADS (COUT * NGROUP)  // 512
#define WSTRIDE (KW + 2)   // 129, odd stride -> conflict-free lane reads

__global__ __launch_bounds__(NTHREADS, 2)
void conv1d_direct_kernel(const float* __restrict__ x,
                          const float* __restrict__ W,
                          float* __restrict__ y) {
    __shared__ float xsh[TT + 128];          // window: [t0-63, t0+TT+63)
    __shared__ float Wsh[COUT * WSTRIDE];    // W[:, i, :] staged per input ch

    const int b   = blockIdx.y;
    const int t0  = blockIdx.x * TT;
    const int tid = threadIdx.x;
    const int o   = tid & 63;                // warp lanes 0..31 -> o 0..31 (same g)
    const int g   = tid >> 6;                // t-group 0..7

    float acc[RR];
    #pragma unroll
    for (int r = 0; r < RR; r++) acc[r] = 0.f;

    for (int i = 0; i < CIN; i++) {
        // --- stage x window for channel i (zero padded) ---
        for (int j = tid; j < TT + 126; j += NTHREADS) {
            int t = t0 - PAD + j;
            xsh[j] = (t >= 0 && t < T_) ? x[(b * CIN + i) * T_ + t] : 0.f;
        }
        // --- stage W[:, i, :] ---
        for (int m = tid; m < COUT * KW; m += NTHREADS) {
            int oo = m / KW;
            int kk = m - oo * KW;
            Wsh[oo * WSTRIDE + kk] = W[(oo * CIN + i) * KW + kk];
        }
        __syncthreads();

        const float* wrow = &Wsh[o * WSTRIDE];
        const float* xrow = &xsh[g * RR];
        // acc[r] += sum_k wrow[k] * xrow[r + 126 - k]

        #pragma unroll 1
        for (int k = 0; k < 124; k += 4) {
            const float w0 = wrow[k], w1 = wrow[k + 1],
                        w2 = wrow[k + 2], w3 = wrow[k + 3];
            const int base = 123 - k;  // pairs with w3
            float xv0 = xrow[base], xv1 = xrow[base + 1], xv2 = xrow[base + 2];
            #pragma unroll
            for (int r = 0; r < RR; r++) {
                const float xv3 = xrow[base + 3 + r];   // 1 LDS per 4 MACs
                acc[r] += w3 * xv0;
                acc[r] += w2 * xv1;
                acc[r] += w1 * xv2;
                acc[r] += w0 * xv3;
                xv0 = xv1; xv1 = xv2; xv2 = xv3;        // renamed away by unroll
            }
        }
        // tail: k = 124, 125, 126
        {
            const float w0 = wrow[124], w1 = wrow[125], w2 = wrow[126];
            float xv0 = xrow[0], xv1 = xrow[1];
            #pragma unroll
            for (int r = 0; r < RR; r++) {
                const float xv2 = xrow[2 + r];
                acc[r] += w2 * xv0;
                acc[r] += w1 * xv1;
                acc[r] += w0 * xv2;
                xv0 = xv1; xv1 = xv2;
            }
        }
        __syncthreads();
    }

    // --- write 16 contiguous floats per thread as 4x float4 ---
    float* yp = &y[(b * COUT + o) * T_ + t0 + g * RR];
    #pragma unroll
    for (int r4 = 0; r4 < RR; r4 += 4) {
        float4 v = make_float4(acc[r4], acc[r4 + 1], acc[r4 + 2], acc[r4 + 3]);
        *reinterpret_cast<float4*>(yp + r4) = v;
    }
}

extern "C" void kernel_launch(void* const* d_in, const int* in_sizes, int n_in,
                              void* d_out, int out_size) {
    const float* x = (const float*)d_in[0];   // [B, CIN, T]
    const float* W = (const float*)d_in[1];   // [COUT, CIN, K]
    float* y       = (float*)d_out;           // [B, COUT, T]
    (void)in_sizes; (void)n_in; (void)out_size;

    dim3 grid(T_ / TT, B_);                    // 128 x 8 = 1024 blocks
    conv1d_direct_kernel<<<grid, NTHREADS>>>(x, W, y);
}